// round 2
// baseline (speedup 1.0000x reference)
#include <cuda_runtime.h>
#include <cstdint>
#include <math.h>

// Problem constants (fixed by the dataset)
#define TT   16384          // tokens = 8*2048
#define DD   768
#define EE   4
#define DFFC 1024

// -------- scratch (no cudaMalloc allowed) --------
__device__ float g_h[TT * DD];        // dense projection output
__device__ float g_act[TT * DFFC];    // gelu(h @ W1[e] + b1[e]) for current expert
__device__ float g_comb[TT * EE];     // dense combine weights (0 for unselected)

// -------- helpers --------
__device__ __forceinline__ uint32_t f32_to_tf32(float x) {
    uint32_t u;
    asm("cvt.rna.tf32.f32 %0, %1;" : "=r"(u) : "f"(x));
    return u;
}

__device__ __forceinline__ float gelu_tanh(float x) {
    // jax.nn.gelu default (approximate=True)
    float x3 = x * x * x;
    return 0.5f * x * (1.0f + tanhf(0.7978845608028654f * (x + 0.044715f * x3)));
}

__device__ __forceinline__ void mma_tf32(float c[4], const uint32_t a[4], const uint32_t b[2]) {
    asm volatile(
        "mma.sync.aligned.m16n8k8.row.col.f32.tf32.tf32.f32 "
        "{%0,%1,%2,%3}, {%4,%5,%6,%7}, {%8,%9}, {%0,%1,%2,%3};\n"
        : "+f"(c[0]), "+f"(c[1]), "+f"(c[2]), "+f"(c[3])
        : "r"(a[0]), "r"(a[1]), "r"(a[2]), "r"(a[3]), "r"(b[0]), "r"(b[1]));
}

// ============================================================================
// SIMT fp32 GEMM with bias: C[M,N] = A[M,K] @ B[K,N] + bias   (router-feeding
// projection; must be fp32-accurate so top-2 selection matches the reference)
// BM=128, BN=64, BK=8, 256 threads, 8x4 outputs per thread.
// ============================================================================
__global__ __launch_bounds__(256) void sgemm_bias_kernel(
    const float* __restrict__ A, const float* __restrict__ B,
    const float* __restrict__ bias, float* __restrict__ C,
    int M, int N, int K)
{
    __shared__ float As[8][128];   // transposed A tile: As[k][m]
    __shared__ float Bs[8][64];    // Bs[k][n]

    const int tid  = threadIdx.x;
    const int bm   = blockIdx.y * 128;
    const int bn   = blockIdx.x * 64;
    const int tidy = tid >> 4;     // 0..15 -> 8 rows each
    const int tidx = tid & 15;     // 0..15 -> 4 cols each

    float acc[8][4];
#pragma unroll
    for (int j = 0; j < 8; j++)
#pragma unroll
        for (int i = 0; i < 4; i++) acc[j][i] = 0.0f;

    const int aRow = tid >> 1;            // 0..127
    const int aCol = (tid & 1) * 4;       // 0 or 4
    const int bRow = tid >> 5;            // 0..7
    const int bCol = (tid & 31) * 2;      // 0..62

    for (int k0 = 0; k0 < K; k0 += 8) {
        float4 av = *(const float4*)(A + (size_t)(bm + aRow) * K + k0 + aCol);
        float2 bv = *(const float2*)(B + (size_t)(k0 + bRow) * N + bn + bCol);
        __syncthreads();
        As[aCol + 0][aRow] = av.x;
        As[aCol + 1][aRow] = av.y;
        As[aCol + 2][aRow] = av.z;
        As[aCol + 3][aRow] = av.w;
        Bs[bRow][bCol + 0] = bv.x;
        Bs[bRow][bCol + 1] = bv.y;
        __syncthreads();
#pragma unroll
        for (int k = 0; k < 8; k++) {
            float4 a0 = *(const float4*)&As[k][tidy * 8];
            float4 a1 = *(const float4*)&As[k][tidy * 8 + 4];
            float4 b0 = *(const float4*)&Bs[k][tidx * 4];
            float a[8] = {a0.x, a0.y, a0.z, a0.w, a1.x, a1.y, a1.z, a1.w};
            float bb[4] = {b0.x, b0.y, b0.z, b0.w};
#pragma unroll
            for (int j = 0; j < 8; j++)
#pragma unroll
                for (int i = 0; i < 4; i++) acc[j][i] += a[j] * bb[i];
        }
    }

    float4 bvv = *(const float4*)&bias[bn + tidx * 4];
#pragma unroll
    for (int j = 0; j < 8; j++) {
        int row = bm + tidy * 8 + j;
        float4 o;
        o.x = acc[j][0] + bvv.x;
        o.y = acc[j][1] + bvv.y;
        o.z = acc[j][2] + bvv.z;
        o.w = acc[j][3] + bvv.w;
        *(float4*)(C + (size_t)row * N + bn + tidx * 4) = o;
    }
}

// ============================================================================
// Router: one warp per token. logits = h[t]@Wg + bg (fp32), softmax, top-2,
// renormalized gates -> dense comb[t, E] (zeros for unselected experts).
// ============================================================================
__global__ __launch_bounds__(256) void router_kernel(
    const float* __restrict__ h, const float* __restrict__ Wg,
    const float* __restrict__ bg, float* __restrict__ comb, int T)
{
    int gwarp = (blockIdx.x * blockDim.x + threadIdx.x) >> 5;
    int lane  = threadIdx.x & 31;
    if (gwarp >= T) return;
    const float* hr = h + (size_t)gwarp * DD;

    float a0 = 0.f, a1 = 0.f, a2 = 0.f, a3 = 0.f;
    for (int d = lane; d < DD; d += 32) {
        float hv = hr[d];
        float4 w = *(const float4*)&Wg[(size_t)d * 4];
        a0 += hv * w.x; a1 += hv * w.y; a2 += hv * w.z; a3 += hv * w.w;
    }
#pragma unroll
    for (int o = 16; o > 0; o >>= 1) {
        a0 += __shfl_xor_sync(0xffffffffu, a0, o);
        a1 += __shfl_xor_sync(0xffffffffu, a1, o);
        a2 += __shfl_xor_sync(0xffffffffu, a2, o);
        a3 += __shfl_xor_sync(0xffffffffu, a3, o);
    }
    if (lane == 0) {
        float l[4] = {a0 + bg[0], a1 + bg[1], a2 + bg[2], a3 + bg[3]};
        int i1 = 0;
#pragma unroll
        for (int e = 1; e < 4; e++) if (l[e] > l[i1]) i1 = e;
        int i2 = (i1 == 0) ? 1 : 0;
#pragma unroll
        for (int e = 0; e < 4; e++) if (e != i1 && l[e] > l[i2]) i2 = e;
        float m  = l[i1];
        float p1 = 1.0f;                 // exp(0)
        float p2 = expf(l[i2] - m);
        float s  = p1 + p2;
        float out[4] = {0.f, 0.f, 0.f, 0.f};
        out[i1] = p1 / s;
        out[i2] = p2 / s;
        *(float4*)&comb[(size_t)gwarp * 4] = make_float4(out[0], out[1], out[2], out[3]);
    }
}

// ============================================================================
// TF32 tensor-core GEMM with fused epilogues.
// C[M,N] = epi(A[M,K] @ B[K,N] + bias)
//   GELU:     v = gelu_tanh(v)
//   ROWSCALE: v *= rowscale[row*4]     (rowscale = comb + e)
//   ACCUM:    C += v  else C = v
// BM=128, BN=64, BK=16; 8 warps in a 4(m) x 2(n) grid of 32x32 warp tiles,
// each warp: 2x4 m16n8k8 mma per k8 step. Double-buffered smem, rna tf32
// conversion on the global->shared path. Padded strides 20 / 72 make the
// fragment LDS conflict-free.
// ============================================================================
template<bool GELU, bool ROWSCALE, bool ACCUM>
__global__ __launch_bounds__(256) void gemm_tf32_kernel(
    const float* __restrict__ A, const float* __restrict__ B,
    const float* __restrict__ bias, const float* __restrict__ rowscale,
    float* __restrict__ C, int M, int N, int K)
{
    __shared__ uint32_t As[2][128][20];
    __shared__ uint32_t Bs[2][16][72];

    const int tid  = threadIdx.x;
    const int bm   = blockIdx.y * 128;
    const int bn   = blockIdx.x * 64;
    const int warp = tid >> 5, lane = tid & 31;
    const int g    = lane >> 2, tig = lane & 3;
    const int wm   = (warp >> 1) * 32;
    const int wn   = (warp & 1) * 32;

    float c[2][4][4];
#pragma unroll
    for (int mt = 0; mt < 2; mt++)
#pragma unroll
        for (int nt = 0; nt < 4; nt++)
#pragma unroll
            for (int i = 0; i < 4; i++) c[mt][nt][i] = 0.0f;

    const int aRow = tid >> 2;          // 0..63
    const int aCol = (tid & 3) * 4;     // 0,4,8,12
    const int bRow = tid >> 4;          // 0..15
    const int bCol = (tid & 15) * 4;    // 0..60

    const float* Aptr0 = A + (size_t)(bm + aRow) * K + aCol;
    const float* Aptr1 = A + (size_t)(bm + aRow + 64) * K + aCol;
    const float* Bptr  = B + (size_t)bRow * N + bn + bCol;

    const int KT = K >> 4;

    // prologue: tile 0
    {
        float4 a0 = *(const float4*)Aptr0;
        float4 a1 = *(const float4*)Aptr1;
        float4 bv = *(const float4*)Bptr;
        As[0][aRow][aCol + 0] = f32_to_tf32(a0.x);
        As[0][aRow][aCol + 1] = f32_to_tf32(a0.y);
        As[0][aRow][aCol + 2] = f32_to_tf32(a0.z);
        As[0][aRow][aCol + 3] = f32_to_tf32(a0.w);
        As[0][aRow + 64][aCol + 0] = f32_to_tf32(a1.x);
        As[0][aRow + 64][aCol + 1] = f32_to_tf32(a1.y);
        As[0][aRow + 64][aCol + 2] = f32_to_tf32(a1.z);
        As[0][aRow + 64][aCol + 3] = f32_to_tf32(a1.w);
        Bs[0][bRow][bCol + 0] = f32_to_tf32(bv.x);
        Bs[0][bRow][bCol + 1] = f32_to_tf32(bv.y);
        Bs[0][bRow][bCol + 2] = f32_to_tf32(bv.z);
        Bs[0][bRow][bCol + 3] = f32_to_tf32(bv.w);
    }
    __syncthreads();

    int cur = 0;
    for (int kt = 0; kt < KT; kt++) {
        float4 na0, na1, nbv;
        const bool has = (kt + 1 < KT);
        if (has) {
            na0 = *(const float4*)(Aptr0 + (kt + 1) * 16);
            na1 = *(const float4*)(Aptr1 + (kt + 1) * 16);
            nbv = *(const float4*)(Bptr + (size_t)(kt + 1) * 16 * N);
        }

#pragma unroll
        for (int ks = 0; ks < 16; ks += 8) {
            uint32_t af[2][4], bf[4][2];
#pragma unroll
            for (int mt = 0; mt < 2; mt++) {
                int r = wm + mt * 16 + g;
                af[mt][0] = As[cur][r][ks + tig];
                af[mt][1] = As[cur][r + 8][ks + tig];
                af[mt][2] = As[cur][r][ks + tig + 4];
                af[mt][3] = As[cur][r + 8][ks + tig + 4];
            }
#pragma unroll
            for (int nt = 0; nt < 4; nt++) {
                int cc = wn + nt * 8 + g;
                bf[nt][0] = Bs[cur][ks + tig][cc];
                bf[nt][1] = Bs[cur][ks + tig + 4][cc];
            }
#pragma unroll
            for (int mt = 0; mt < 2; mt++)
#pragma unroll
                for (int nt = 0; nt < 4; nt++)
                    mma_tf32(c[mt][nt], af[mt], bf[nt]);
        }

        if (has) {
            int nb = cur ^ 1;
            As[nb][aRow][aCol + 0] = f32_to_tf32(na0.x);
            As[nb][aRow][aCol + 1] = f32_to_tf32(na0.y);
            As[nb][aRow][aCol + 2] = f32_to_tf32(na0.z);
            As[nb][aRow][aCol + 3] = f32_to_tf32(na0.w);
            As[nb][aRow + 64][aCol + 0] = f32_to_tf32(na1.x);
            As[nb][aRow + 64][aCol + 1] = f32_to_tf32(na1.y);
            As[nb][aRow + 64][aCol + 2] = f32_to_tf32(na1.z);
            As[nb][aRow + 64][aCol + 3] = f32_to_tf32(na1.w);
            Bs[nb][bRow][bCol + 0] = f32_to_tf32(nbv.x);
            Bs[nb][bRow][bCol + 1] = f32_to_tf32(nbv.y);
            Bs[nb][bRow][bCol + 2] = f32_to_tf32(nbv.z);
            Bs[nb][bRow][bCol + 3] = f32_to_tf32(nbv.w);
            __syncthreads();
            cur = nb;
        }
    }

    // epilogue
#pragma unroll
    for (int mt = 0; mt < 2; mt++) {
        int r0 = bm + wm + mt * 16 + g;
        int r1 = r0 + 8;
        float s0 = 1.0f, s1 = 1.0f;
        if (ROWSCALE) {
            s0 = rowscale[(size_t)r0 * 4];
            s1 = rowscale[(size_t)r1 * 4];
        }
#pragma unroll
        for (int nt = 0; nt < 4; nt++) {
            int c0 = bn + wn + nt * 8 + tig * 2;
            float b0v = bias[c0], b1v = bias[c0 + 1];
            float v00 = c[mt][nt][0] + b0v;
            float v01 = c[mt][nt][1] + b1v;
            float v10 = c[mt][nt][2] + b0v;
            float v11 = c[mt][nt][3] + b1v;
            if (GELU) {
                v00 = gelu_tanh(v00); v01 = gelu_tanh(v01);
                v10 = gelu_tanh(v10); v11 = gelu_tanh(v11);
            }
            if (ROWSCALE) {
                v00 *= s0; v01 *= s0; v10 *= s1; v11 *= s1;
            }
            size_t o0 = (size_t)r0 * N + c0;
            size_t o1 = (size_t)r1 * N + c0;
            if (ACCUM) {
                C[o0] += v00; C[o0 + 1] += v01;
                C[o1] += v10; C[o1 + 1] += v11;
            } else {
                C[o0] = v00; C[o0 + 1] = v01;
                C[o1] = v10; C[o1 + 1] = v11;
            }
        }
    }
}

// ============================================================================
// launch
// ============================================================================
extern "C" void kernel_launch(void* const* d_in, const int* in_sizes, int n_in,
                              void* d_out, int out_size)
{
    const float* X  = (const float*)d_in[0];   // [8,2048,768]
    const float* W  = (const float*)d_in[1];   // [768,768]
    const float* b  = (const float*)d_in[2];   // [768]
    const float* Wg = (const float*)d_in[3];   // [768,4]
    const float* bg = (const float*)d_in[4];   // [4]
    const float* W1 = (const float*)d_in[5];   // [4,768,1024]
    const float* b1 = (const float*)d_in[6];   // [4,1024]
    const float* W2 = (const float*)d_in[7];   // [4,1024,768]
    const float* b2 = (const float*)d_in[8];   // [4,768]
    float* out = (float*)d_out;

    const int T = in_sizes[0] / DD;            // 16384

    float *h, *act, *comb;
    cudaGetSymbolAddress((void**)&h,    g_h);
    cudaGetSymbolAddress((void**)&act,  g_act);
    cudaGetSymbolAddress((void**)&comb, g_comb);

    // 1) dense projection (fp32 SIMT — router-critical precision)
    sgemm_bias_kernel<<<dim3(DD / 64, T / 128), 256>>>(X, W, b, h, T, DD, DD);

    // 2) router -> dense combine weights
    router_kernel<<<T / 8, 256>>>(h, Wg, bg, comb, T);

    // 3) experts (tf32 tensor cores)
    for (int e = 0; e < EE; e++) {
        const float* W1e = W1 + (size_t)e * DD * DFFC;
        const float* b1e = b1 + (size_t)e * DFFC;
        const float* W2e = W2 + (size_t)e * DFFC * DD;
        const float* b2e = b2 + (size_t)e * DD;

        // act = gelu(h @ W1[e] + b1[e])
        gemm_tf32_kernel<true, false, false>
            <<<dim3(DFFC / 64, T / 128), 256>>>(h, W1e, b1e, nullptr, act, T, DFFC, DD);

        // out (+)= comb[:,e] * (act @ W2[e] + b2[e])
        if (e == 0)
            gemm_tf32_kernel<false, true, false>
                <<<dim3(DD / 64, T / 128), 256>>>(act, W2e, b2e, comb + e, out, T, DD, DFFC);
        else
            gemm_tf32_kernel<false, true, true>
                <<<dim3(DD / 64, T / 128), 256>>>(act, W2e, b2e, comb + e, out, T, DD, DFFC);
    }
}

// round 6
// speedup vs baseline: 1.5990x; 1.5990x over previous
#include <cuda_runtime.h>
#include <cstdint>
#include <math.h>

// Problem constants (fixed by the dataset)
#define TT   16384          // tokens = 8*2048
#define DD   768
#define EE   4
#define DFFC 1024

// -------- scratch (no cudaMalloc allowed) --------
__device__ float g_h[TT * DD];          // dense projection output
__device__ float g_act[TT * DFFC];      // gelu(h_gathered @ W1[e] + b1[e]), compacted per expert
__device__ int   g_idx[EE * TT];        // compacted row -> original token
__device__ float g_gate[EE * TT];       // compacted row -> gate
__device__ int   g_cnt[EE];             // tokens routed to each expert

// -------- helpers --------
__device__ __forceinline__ uint32_t f32_to_tf32(float x) {
    uint32_t u;
    asm("cvt.rna.tf32.f32 %0, %1;" : "=r"(u) : "f"(x));
    return u;
}

__device__ __forceinline__ float gelu_tanh(float x) {
    float x3 = x * x * x;
    return 0.5f * x * (1.0f + tanhf(0.7978845608028654f * (x + 0.044715f * x3)));
}

__device__ __forceinline__ void mma_tf32(float c[4], const uint32_t a[4], const uint32_t b[2]) {
    asm volatile(
        "mma.sync.aligned.m16n8k8.row.col.f32.tf32.tf32.f32 "
        "{%0,%1,%2,%3}, {%4,%5,%6,%7}, {%8,%9}, {%0,%1,%2,%3};\n"
        : "+f"(c[0]), "+f"(c[1]), "+f"(c[2]), "+f"(c[3])
        : "r"(a[0]), "r"(a[1]), "r"(a[2]), "r"(a[3]), "r"(b[0]), "r"(b[1]));
}

// ============================================================================
// init: zero counters and index/gate lists (pads map to token 0, gate 0)
// ============================================================================
__global__ void init_kernel(int* __restrict__ cnt, int* __restrict__ idxL,
                            float* __restrict__ gateL)
{
    int i = blockIdx.x * blockDim.x + threadIdx.x;
    if (i < EE) cnt[i] = 0;
    if (i < EE * TT) { idxL[i] = 0; gateL[i] = 0.0f; }
}

// ============================================================================
// SIMT fp32 GEMM with bias (router-critical precision): h = X @ W + b
// BM=128, BN=64, BK=8, 256 threads. (unchanged from R1 — validated)
// ============================================================================
__global__ __launch_bounds__(256) void sgemm_bias_kernel(
    const float* __restrict__ A, const float* __restrict__ B,
    const float* __restrict__ bias, float* __restrict__ C,
    int M, int N, int K)
{
    __shared__ float As[8][128];
    __shared__ float Bs[8][64];

    const int tid  = threadIdx.x;
    const int bm   = blockIdx.y * 128;
    const int bn   = blockIdx.x * 64;
    const int tidy = tid >> 4;
    const int tidx = tid & 15;

    float acc[8][4];
#pragma unroll
    for (int j = 0; j < 8; j++)
#pragma unroll
        for (int i = 0; i < 4; i++) acc[j][i] = 0.0f;

    const int aRow = tid >> 1;
    const int aCol = (tid & 1) * 4;
    const int bRow = tid >> 5;
    const int bCol = (tid & 31) * 2;

    for (int k0 = 0; k0 < K; k0 += 8) {
        float4 av = *(const float4*)(A + (size_t)(bm + aRow) * K + k0 + aCol);
        float2 bv = *(const float2*)(B + (size_t)(k0 + bRow) * N + bn + bCol);
        __syncthreads();
        As[aCol + 0][aRow] = av.x;
        As[aCol + 1][aRow] = av.y;
        As[aCol + 2][aRow] = av.z;
        As[aCol + 3][aRow] = av.w;
        Bs[bRow][bCol + 0] = bv.x;
        Bs[bRow][bCol + 1] = bv.y;
        __syncthreads();
#pragma unroll
        for (int k = 0; k < 8; k++) {
            float4 a0 = *(const float4*)&As[k][tidy * 8];
            float4 a1 = *(const float4*)&As[k][tidy * 8 + 4];
            float4 b0 = *(const float4*)&Bs[k][tidx * 4];
            float a[8] = {a0.x, a0.y, a0.z, a0.w, a1.x, a1.y, a1.z, a1.w};
            float bb[4] = {b0.x, b0.y, b0.z, b0.w};
#pragma unroll
            for (int j = 0; j < 8; j++)
#pragma unroll
                for (int i = 0; i < 4; i++) acc[j][i] += a[j] * bb[i];
        }
    }

    float4 bvv = *(const float4*)&bias[bn + tidx * 4];
#pragma unroll
    for (int j = 0; j < 8; j++) {
        int row = bm + tidy * 8 + j;
        float4 o;
        o.x = acc[j][0] + bvv.x;
        o.y = acc[j][1] + bvv.y;
        o.z = acc[j][2] + bvv.z;
        o.w = acc[j][3] + bvv.w;
        *(float4*)(C + (size_t)row * N + bn + tidx * 4) = o;
    }
}

// ============================================================================
// Router: one warp per token. fp32 logits, top-2, renormalized gates.
// Emits compacted per-expert (token, gate) lists via global atomics.
// Order of compacted rows is nondeterministic; output values are not
// (each token's contribution is independent of list position).
// ============================================================================
__global__ __launch_bounds__(256) void router_kernel(
    const float* __restrict__ h, const float* __restrict__ Wg,
    const float* __restrict__ bg, int* __restrict__ idxL,
    float* __restrict__ gateL, int* __restrict__ cnt, int T)
{
    int tok  = (blockIdx.x * blockDim.x + threadIdx.x) >> 5;
    int lane = threadIdx.x & 31;
    if (tok >= T) return;
    const float* hr = h + (size_t)tok * DD;

    float a0 = 0.f, a1 = 0.f, a2 = 0.f, a3 = 0.f;
    for (int d = lane; d < DD; d += 32) {
        float hv = hr[d];
        float4 w = *(const float4*)&Wg[(size_t)d * 4];
        a0 += hv * w.x; a1 += hv * w.y; a2 += hv * w.z; a3 += hv * w.w;
    }
#pragma unroll
    for (int o = 16; o > 0; o >>= 1) {
        a0 += __shfl_xor_sync(0xffffffffu, a0, o);
        a1 += __shfl_xor_sync(0xffffffffu, a1, o);
        a2 += __shfl_xor_sync(0xffffffffu, a2, o);
        a3 += __shfl_xor_sync(0xffffffffu, a3, o);
    }
    if (lane == 0) {
        float l[4] = {a0 + bg[0], a1 + bg[1], a2 + bg[2], a3 + bg[3]};
        int i1 = 0;
#pragma unroll
        for (int e = 1; e < 4; e++) if (l[e] > l[i1]) i1 = e;
        int i2 = (i1 == 0) ? 1 : 0;
#pragma unroll
        for (int e = 0; e < 4; e++) if (e != i1 && l[e] > l[i2]) i2 = e;
        float p2 = expf(l[i2] - l[i1]);
        float s  = 1.0f + p2;
        float g1 = 1.0f / s;
        float g2 = p2 / s;

        int p = atomicAdd(&cnt[i1], 1);
        idxL[i1 * TT + p]  = tok;
        gateL[i1 * TT + p] = g1;
        p = atomicAdd(&cnt[i2], 1);
        idxL[i2 * TT + p]  = tok;
        gateL[i2 * TT + p] = g2;
    }
}

// ============================================================================
// TF32 tensor-core GEMM over compacted expert rows.
// BM=128, BN=128, BK=16; 8 warps as 4(m) x 2(n), warp tile 32x64
// (2x8 m16n8k8 mma per k8 step -> 24 LDS per 16 mmas = 1.5 LDS/mma).
// Double-buffered smem, rna tf32 on the global->shared path.
// GATHER_A: A row rc comes from Adense[idxL[rc]]   (GEMM1: A = h)
// GELU:     v = gelu_tanh(v)                        (GEMM1)
// SCATTER:  C[idxL[rc]] += gateL[rc] * v, guarded by rc < count (GEMM2)
//   else:   C[rc] = v (compacted output, pads written harmlessly)
// Blocks with bm >= count exit immediately (dynamic M, fixed grid).
// ============================================================================
template<bool GATHER_A, bool GELU, bool SCATTER>
__global__ __launch_bounds__(256) void gemm_tf32_moe(
    const float* __restrict__ A, const float* __restrict__ B,
    const float* __restrict__ bias,
    const int* __restrict__ idxL, const float* __restrict__ gateL,
    const int* __restrict__ countp,
    float* __restrict__ C, int N, int K)
{
    __shared__ uint32_t As[2][128][20];
    __shared__ uint32_t Bs[2][16][136];

    const int count = *countp;
    const int bm = blockIdx.y * 128;
    if (bm >= count) return;
    const int bn = blockIdx.x * 128;

    const int tid  = threadIdx.x;
    const int warp = tid >> 5, lane = tid & 31;
    const int g    = lane >> 2, tig = lane & 3;
    const int wm   = (warp >> 1) * 32;   // 0,32,64,96
    const int wn   = (warp & 1) * 64;    // 0,64

    float c[2][8][4];
#pragma unroll
    for (int mt = 0; mt < 2; mt++)
#pragma unroll
        for (int nt = 0; nt < 8; nt++)
#pragma unroll
            for (int i = 0; i < 4; i++) c[mt][nt][i] = 0.0f;

    const int aRow = tid >> 1;          // 0..127 (one tile row per thread)
    const int aCol = (tid & 1) * 8;     // 0 or 8
    const int bRow = tid >> 4;          // 0..15
    const int bCol = (tid & 15) * 8;    // 0..120

    int arow = bm + aRow;               // compacted row
    if (GATHER_A) arow = idxL[arow];    // pads -> token 0 (safe loads)
    const float* Aptr = A + (size_t)arow * K + aCol;
    const float* Bptr = B + (size_t)bRow * N + bn + bCol;

    const int KT = K >> 4;

    // prologue: tile 0
    {
        float4 a0 = *(const float4*)(Aptr);
        float4 a1 = *(const float4*)(Aptr + 4);
        float4 b0 = *(const float4*)(Bptr);
        float4 b1 = *(const float4*)(Bptr + 4);
        As[0][aRow][aCol + 0] = f32_to_tf32(a0.x);
        As[0][aRow][aCol + 1] = f32_to_tf32(a0.y);
        As[0][aRow][aCol + 2] = f32_to_tf32(a0.z);
        As[0][aRow][aCol + 3] = f32_to_tf32(a0.w);
        As[0][aRow][aCol + 4] = f32_to_tf32(a1.x);
        As[0][aRow][aCol + 5] = f32_to_tf32(a1.y);
        As[0][aRow][aCol + 6] = f32_to_tf32(a1.z);
        As[0][aRow][aCol + 7] = f32_to_tf32(a1.w);
        Bs[0][bRow][bCol + 0] = f32_to_tf32(b0.x);
        Bs[0][bRow][bCol + 1] = f32_to_tf32(b0.y);
        Bs[0][bRow][bCol + 2] = f32_to_tf32(b0.z);
        Bs[0][bRow][bCol + 3] = f32_to_tf32(b0.w);
        Bs[0][bRow][bCol + 4] = f32_to_tf32(b1.x);
        Bs[0][bRow][bCol + 5] = f32_to_tf32(b1.y);
        Bs[0][bRow][bCol + 6] = f32_to_tf32(b1.z);
        Bs[0][bRow][bCol + 7] = f32_to_tf32(b1.w);
    }
    __syncthreads();

    int cur = 0;
    for (int kt = 0; kt < KT; kt++) {
        float4 na0, na1, nb0, nb1;
        const bool has = (kt + 1 < KT);
        if (has) {
            na0 = *(const float4*)(Aptr + (kt + 1) * 16);
            na1 = *(const float4*)(Aptr + (kt + 1) * 16 + 4);
            nb0 = *(const float4*)(Bptr + (size_t)(kt + 1) * 16 * N);
            nb1 = *(const float4*)(Bptr + (size_t)(kt + 1) * 16 * N + 4);
        }

#pragma unroll
        for (int ks = 0; ks < 16; ks += 8) {
            uint32_t af[2][4], bf[8][2];
#pragma unroll
            for (int mt = 0; mt < 2; mt++) {
                int r = wm + mt * 16 + g;
                af[mt][0] = As[cur][r][ks + tig];
                af[mt][1] = As[cur][r + 8][ks + tig];
                af[mt][2] = As[cur][r][ks + tig + 4];
                af[mt][3] = As[cur][r + 8][ks + tig + 4];
            }
#pragma unroll
            for (int nt = 0; nt < 8; nt++) {
                int cc = wn + nt * 8 + g;
                bf[nt][0] = Bs[cur][ks + tig][cc];
                bf[nt][1] = Bs[cur][ks + tig + 4][cc];
            }
#pragma unroll
            for (int mt = 0; mt < 2; mt++)
#pragma unroll
                for (int nt = 0; nt < 8; nt++)
                    mma_tf32(c[mt][nt], af[mt], bf[nt]);
        }

        if (has) {
            int nb = cur ^ 1;
            As[nb][aRow][aCol + 0] = f32_to_tf32(na0.x);
            As[nb][aRow][aCol + 1] = f32_to_tf32(na0.y);
            As[nb][aRow][aCol + 2] = f32_to_tf32(na0.z);
            As[nb][aRow][aCol + 3] = f32_to_tf32(na0.w);
            As[nb][aRow][aCol + 4] = f32_to_tf32(na1.x);
            As[nb][aRow][aCol + 5] = f32_to_tf32(na1.y);
            As[nb][aRow][aCol + 6] = f32_to_tf32(na1.z);
            As[nb][aRow][aCol + 7] = f32_to_tf32(na1.w);
            Bs[nb][bRow][bCol + 0] = f32_to_tf32(nb0.x);
            Bs[nb][bRow][bCol + 1] = f32_to_tf32(nb0.y);
            Bs[nb][bRow][bCol + 2] = f32_to_tf32(nb0.z);
            Bs[nb][bRow][bCol + 3] = f32_to_tf32(nb0.w);
            Bs[nb][bRow][bCol + 4] = f32_to_tf32(nb1.x);
            Bs[nb][bRow][bCol + 5] = f32_to_tf32(nb1.y);
            Bs[nb][bRow][bCol + 6] = f32_to_tf32(nb1.z);
            Bs[nb][bRow][bCol + 7] = f32_to_tf32(nb1.w);
            __syncthreads();
            cur = nb;
        }
    }

    // epilogue
#pragma unroll
    for (int mt = 0; mt < 2; mt++) {
        int rc0 = bm + wm + mt * 16 + g;
        int rc1 = rc0 + 8;
        bool v0 = true, v1 = true;
        int row0 = rc0, row1 = rc1;
        float s0 = 1.0f, s1 = 1.0f;
        if (SCATTER) {
            v0 = rc0 < count;
            v1 = rc1 < count;
            row0 = v0 ? idxL[rc0] : 0;
            row1 = v1 ? idxL[rc1] : 0;
            s0 = v0 ? gateL[rc0] : 0.0f;
            s1 = v1 ? gateL[rc1] : 0.0f;
        }
#pragma unroll
        for (int nt = 0; nt < 8; nt++) {
            int c0 = bn + wn + nt * 8 + tig * 2;
            float b0v = bias[c0], b1v = bias[c0 + 1];
            float v00 = c[mt][nt][0] + b0v;
            float v01 = c[mt][nt][1] + b1v;
            float v10 = c[mt][nt][2] + b0v;
            float v11 = c[mt][nt][3] + b1v;
            if (GELU) {
                v00 = gelu_tanh(v00); v01 = gelu_tanh(v01);
                v10 = gelu_tanh(v10); v11 = gelu_tanh(v11);
            }
            if (SCATTER) {
                if (v0) {
                    size_t o0 = (size_t)row0 * N + c0;
                    C[o0]     += s0 * v00;
                    C[o0 + 1] += s0 * v01;
                }
                if (v1) {
                    size_t o1 = (size_t)row1 * N + c0;
                    C[o1]     += s1 * v10;
                    C[o1 + 1] += s1 * v11;
                }
            } else {
                size_t o0 = (size_t)row0 * N + c0;
                size_t o1 = (size_t)row1 * N + c0;
                C[o0]     = v00;
                C[o0 + 1] = v01;
                C[o1]     = v10;
                C[o1 + 1] = v11;
            }
        }
    }
}

// ============================================================================
// launch
// ============================================================================
extern "C" void kernel_launch(void* const* d_in, const int* in_sizes, int n_in,
                              void* d_out, int out_size)
{
    const float* X  = (const float*)d_in[0];   // [8,2048,768]
    const float* W  = (const float*)d_in[1];   // [768,768]
    const float* b  = (const float*)d_in[2];   // [768]
    const float* Wg = (const float*)d_in[3];   // [768,4]
    const float* bg = (const float*)d_in[4];   // [4]
    const float* W1 = (const float*)d_in[5];   // [4,768,1024]
    const float* b1 = (const float*)d_in[6];   // [4,1024]
    const float* W2 = (const float*)d_in[7];   // [4,1024,768]
    const float* b2 = (const float*)d_in[8];   // [4,768]
    float* out = (float*)d_out;

    const int T = in_sizes[0] / DD;            // 16384

    float *h, *act, *gate;
    int *idx, *cnt;
    cudaGetSymbolAddress((void**)&h,    g_h);
    cudaGetSymbolAddress((void**)&act,  g_act);
    cudaGetSymbolAddress((void**)&idx,  g_idx);
    cudaGetSymbolAddress((void**)&gate, g_gate);
    cudaGetSymbolAddress((void**)&cnt,  g_cnt);

    // 0) zero output (scatter-accumulated) and routing state
    cudaMemsetAsync(out, 0, sizeof(float) * (size_t)T * DD);
    init_kernel<<<(EE * TT + 255) / 256, 256>>>(cnt, idx, gate);

    // 1) dense projection (fp32 SIMT — router-critical precision)
    sgemm_bias_kernel<<<dim3(DD / 64, T / 128), 256>>>(X, W, b, h, T, DD, DD);

    // 2) router -> compacted per-expert token/gate lists
    router_kernel<<<T / 8, 256>>>(h, Wg, bg, idx, gate, cnt, T);

    // 3) experts (tf32 tensor cores, only routed tokens)
    for (int e = 0; e < EE; e++) {
        const float* W1e = W1 + (size_t)e * DD * DFFC;
        const float* b1e = b1 + (size_t)e * DFFC;
        const float* W2e = W2 + (size_t)e * DFFC * DD;
        const float* b2e = b2 + (size_t)e * DD;

        // act[rc] = gelu(h[idx[rc]] @ W1[e] + b1[e])
        gemm_tf32_moe<true, true, false>
            <<<dim3(DFFC / 128, T / 128), 256>>>(
                h, W1e, b1e, idx + e * TT, nullptr, cnt + e, act, DFFC, DD);

        // out[idx[rc]] += gate[rc] * (act[rc] @ W2[e] + b2[e])
        gemm_tf32_moe<false, false, true>
            <<<dim3(DD / 128, T / 128), 256>>>(
                act, W2e, b2e, idx + e * TT, gate + e * TT, cnt + e, out, DD, DFFC);
    }
}

// round 8
// speedup vs baseline: 2.1926x; 1.3713x over previous
#include <cuda_runtime.h>
#include <cstdint>
#include <math.h>

// Problem constants (fixed by the dataset)
#define TT   16384          // tokens = 8*2048
#define DD   768
#define EE   4
#define DFFC 1024

// -------- scratch (no cudaMalloc allowed) --------
__device__ float g_h[TT * DD];                 // dense projection output (tf32-accurate)
__device__ float g_act[(size_t)EE * TT * DFFC];// per-expert compacted gelu activations
__device__ int   g_idx[EE * TT];               // compacted row -> original token
__device__ float g_gate[EE * TT];              // compacted row -> gate
__device__ int   g_cnt[EE + 1];                // per-expert counts; [EE] = T (dense count)
__device__ float g_Wf[DD * 4];                 // fused router weight W @ Wg
__device__ float g_bf[4];                      // fused router bias b @ Wg + bg

// -------- helpers --------
__device__ __forceinline__ uint32_t f32_to_tf32(float x) {
    uint32_t u;
    asm("cvt.rna.tf32.f32 %0, %1;" : "=r"(u) : "f"(x));
    return u;
}

__device__ __forceinline__ float gelu_tanh(float x) {
    float x3 = x * x * x;
    return 0.5f * x * (1.0f + tanhf(0.7978845608028654f * (x + 0.044715f * x3)));
}

__device__ __forceinline__ void mma_tf32(float c[4], const uint32_t a[4], const uint32_t b[2]) {
    asm volatile(
        "mma.sync.aligned.m16n8k8.row.col.f32.tf32.tf32.f32 "
        "{%0,%1,%2,%3}, {%4,%5,%6,%7}, {%8,%9}, {%0,%1,%2,%3};\n"
        : "+f"(c[0]), "+f"(c[1]), "+f"(c[2]), "+f"(c[3])
        : "r"(a[0]), "r"(a[1]), "r"(a[2]), "r"(a[3]), "r"(b[0]), "r"(b[1]));
}

// vector f32x2 global reduction (no return). Exactly 2 adds land on each output
// element (top-2 routing) on a zeroed buffer; 2-operand fp add is commutative,
// so result is bit-deterministic regardless of atomic order.
__device__ __forceinline__ void red_add_v2(float* p, float x, float y) {
    asm volatile(
        "{\n\t.reg .u64 pg;\n\t"
        "cvta.to.global.u64 pg, %0;\n\t"
        "red.global.add.v2.f32 [pg], {%1, %2};\n\t}"
        :: "l"(p), "f"(x), "f"(y) : "memory");
}

// ============================================================================
// init: zero counters and index/gate lists (pads map to token 0, gate 0);
// cnt[EE] = TT serves as the "dense" row count for the projection GEMM.
// ============================================================================
__global__ void init_kernel(int* __restrict__ cnt, int* __restrict__ idxL,
                            float* __restrict__ gateL)
{
    int i = blockIdx.x * blockDim.x + threadIdx.x;
    if (i < EE) cnt[i] = 0;
    if (i == EE) cnt[EE] = TT;
    if (i < EE * TT) { idxL[i] = 0; gateL[i] = 0.0f; }
}

// ============================================================================
// Router-weight fusion: Wf = W @ Wg  [DD,4],  bf = b @ Wg + bg  [4]
// One warp per output row (fp32, warp-strided + tree reduce).
// ============================================================================
__global__ __launch_bounds__(256) void fuse_wg_kernel(
    const float* __restrict__ W, const float* __restrict__ Wg,
    const float* __restrict__ b, const float* __restrict__ bg,
    float* __restrict__ Wf, float* __restrict__ bf)
{
    int warp = (blockIdx.x * blockDim.x + threadIdx.x) >> 5;
    int lane = threadIdx.x & 31;
    if (warp > DD) return;

    const float* row = (warp < DD) ? (W + (size_t)warp * DD) : b;

    float a0 = 0.f, a1 = 0.f, a2 = 0.f, a3 = 0.f;
    for (int e = lane; e < DD; e += 32) {
        float w = row[e];
        float4 wg = *(const float4*)&Wg[(size_t)e * 4];
        a0 += w * wg.x; a1 += w * wg.y; a2 += w * wg.z; a3 += w * wg.w;
    }
#pragma unroll
    for (int o = 16; o > 0; o >>= 1) {
        a0 += __shfl_xor_sync(0xffffffffu, a0, o);
        a1 += __shfl_xor_sync(0xffffffffu, a1, o);
        a2 += __shfl_xor_sync(0xffffffffu, a2, o);
        a3 += __shfl_xor_sync(0xffffffffu, a3, o);
    }
    if (lane == 0) {
        if (warp < DD) {
            *(float4*)&Wf[(size_t)warp * 4] = make_float4(a0, a1, a2, a3);
        } else {
            bf[0] = a0 + bg[0]; bf[1] = a1 + bg[1];
            bf[2] = a2 + bg[2]; bf[3] = a3 + bg[3];
        }
    }
}

// ============================================================================
// Router: one warp per token, logits = X[t] @ Wf + bf directly from the INPUT
// (mathematically = (X@W+b)@Wg+bg; fp32 accuracy preserved for top-2 choice).
// Emits compacted per-expert (token, gate) lists via global atomics.
// ============================================================================
__global__ __launch_bounds__(256) void router_kernel(
    const float* __restrict__ X, const float* __restrict__ Wf,
    const float* __restrict__ bf, int* __restrict__ idxL,
    float* __restrict__ gateL, int* __restrict__ cnt, int T)
{
    int tok  = (blockIdx.x * blockDim.x + threadIdx.x) >> 5;
    int lane = threadIdx.x & 31;
    if (tok >= T) return;
    const float* xr = X + (size_t)tok * DD;

    float a0 = 0.f, a1 = 0.f, a2 = 0.f, a3 = 0.f;
    for (int d = lane; d < DD; d += 32) {
        float xv = xr[d];
        float4 w = *(const float4*)&Wf[(size_t)d * 4];
        a0 += xv * w.x; a1 += xv * w.y; a2 += xv * w.z; a3 += xv * w.w;
    }
#pragma unroll
    for (int o = 16; o > 0; o >>= 1) {
        a0 += __shfl_xor_sync(0xffffffffu, a0, o);
        a1 += __shfl_xor_sync(0xffffffffu, a1, o);
        a2 += __shfl_xor_sync(0xffffffffu, a2, o);
        a3 += __shfl_xor_sync(0xffffffffu, a3, o);
    }
    if (lane == 0) {
        float l[4] = {a0 + bf[0], a1 + bf[1], a2 + bf[2], a3 + bf[3]};
        int i1 = 0;
#pragma unroll
        for (int e = 1; e < 4; e++) if (l[e] > l[i1]) i1 = e;
        int i2 = (i1 == 0) ? 1 : 0;
#pragma unroll
        for (int e = 0; e < 4; e++) if (e != i1 && l[e] > l[i2]) i2 = e;
        float p2 = expf(l[i2] - l[i1]);
        float s  = 1.0f + p2;
        float g1 = 1.0f / s;
        float g2 = p2 / s;

        int p = atomicAdd(&cnt[i1], 1);
        idxL[i1 * TT + p]  = tok;
        gateL[i1 * TT + p] = g1;
        p = atomicAdd(&cnt[i2], 1);
        idxL[i2 * TT + p]  = tok;
        gateL[i2 * TT + p] = g2;
    }
}

// ============================================================================
// TF32 tensor-core GEMM over (optionally expert-batched, optionally compacted)
// rows. BM=128, BN=128, BK=16; 8 warps as 4(m) x 2(n), warp tile 32x64.
// EBATCH:   e = blockIdx.z selects expert slices of B/bias/idx/gate/count
//           (and of A for GEMM2, of C for GEMM1).
// GATHER_A: A row rc comes from Adense[idxL[rc]]       (GEMM1: A = h)
// GELU:     v = gelu_tanh(v)                           (GEMM1)
// SCATTER:  out[idxL[rc]] += gate[rc]*v via red.v2     (GEMM2)
//   else:   C[rc] = v (dense/compacted write)
// ============================================================================
template<bool GATHER_A, bool GELU, bool SCATTER, bool EBATCH>
__global__ __launch_bounds__(256) void gemm_tf32_moe(
    const float* __restrict__ A, const float* __restrict__ B,
    const float* __restrict__ bias,
    const int* __restrict__ idxL, const float* __restrict__ gateL,
    const int* __restrict__ countp,
    float* __restrict__ C, int N, int K)
{
    __shared__ uint32_t As[2][128][20];
    __shared__ uint32_t Bs[2][16][136];

    if (EBATCH) {
        const int e = blockIdx.z;
        B      += (size_t)e * K * N;
        bias   += (size_t)e * N;
        idxL   += e * TT;
        countp += e;
        if (SCATTER) gateL += e * TT;
        if (GATHER_A) C += (size_t)e * TT * N;   // GEMM1: compacted act slice
        else          A += (size_t)e * TT * K;   // GEMM2: compacted act slice
    }

    const int count = *countp;
    const int bm = blockIdx.y * 128;
    if (bm >= count) return;
    const int bn = blockIdx.x * 128;

    const int tid  = threadIdx.x;
    const int warp = tid >> 5, lane = tid & 31;
    const int g    = lane >> 2, tig = lane & 3;
    const int wm   = (warp >> 1) * 32;   // 0,32,64,96
    const int wn   = (warp & 1) * 64;    // 0,64

    float c[2][8][4];
#pragma unroll
    for (int mt = 0; mt < 2; mt++)
#pragma unroll
        for (int nt = 0; nt < 8; nt++)
#pragma unroll
            for (int i = 0; i < 4; i++) c[mt][nt][i] = 0.0f;

    const int aRow = tid >> 1;          // 0..127
    const int aCol = (tid & 1) * 8;     // 0 or 8
    const int bRow = tid >> 4;          // 0..15
    const int bCol = (tid & 15) * 8;    // 0..120

    int arow = bm + aRow;               // compacted row
    if (GATHER_A) arow = idxL[arow];    // pads -> token 0 (safe loads)
    const float* Aptr = A + (size_t)arow * K + aCol;
    const float* Bptr = B + (size_t)bRow * N + bn + bCol;

    const int KT = K >> 4;

    // prologue: tile 0
    {
        float4 a0 = *(const float4*)(Aptr);
        float4 a1 = *(const float4*)(Aptr + 4);
        float4 b0 = *(const float4*)(Bptr);
        float4 b1 = *(const float4*)(Bptr + 4);
        As[0][aRow][aCol + 0] = f32_to_tf32(a0.x);
        As[0][aRow][aCol + 1] = f32_to_tf32(a0.y);
        As[0][aRow][aCol + 2] = f32_to_tf32(a0.z);
        As[0][aRow][aCol + 3] = f32_to_tf32(a0.w);
        As[0][aRow][aCol + 4] = f32_to_tf32(a1.x);
        As[0][aRow][aCol + 5] = f32_to_tf32(a1.y);
        As[0][aRow][aCol + 6] = f32_to_tf32(a1.z);
        As[0][aRow][aCol + 7] = f32_to_tf32(a1.w);
        Bs[0][bRow][bCol + 0] = f32_to_tf32(b0.x);
        Bs[0][bRow][bCol + 1] = f32_to_tf32(b0.y);
        Bs[0][bRow][bCol + 2] = f32_to_tf32(b0.z);
        Bs[0][bRow][bCol + 3] = f32_to_tf32(b0.w);
        Bs[0][bRow][bCol + 4] = f32_to_tf32(b1.x);
        Bs[0][bRow][bCol + 5] = f32_to_tf32(b1.y);
        Bs[0][bRow][bCol + 6] = f32_to_tf32(b1.z);
        Bs[0][bRow][bCol + 7] = f32_to_tf32(b1.w);
    }
    __syncthreads();

    int cur = 0;
    for (int kt = 0; kt < KT; kt++) {
        float4 na0, na1, nb0, nb1;
        const bool has = (kt + 1 < KT);
        if (has) {
            na0 = *(const float4*)(Aptr + (kt + 1) * 16);
            na1 = *(const float4*)(Aptr + (kt + 1) * 16 + 4);
            nb0 = *(const float4*)(Bptr + (size_t)(kt + 1) * 16 * N);
            nb1 = *(const float4*)(Bptr + (size_t)(kt + 1) * 16 * N + 4);
        }

#pragma unroll
        for (int ks = 0; ks < 16; ks += 8) {
            uint32_t af[2][4], bf[8][2];
#pragma unroll
            for (int mt = 0; mt < 2; mt++) {
                int r = wm + mt * 16 + g;
                af[mt][0] = As[cur][r][ks + tig];
                af[mt][1] = As[cur][r + 8][ks + tig];
                af[mt][2] = As[cur][r][ks + tig + 4];
                af[mt][3] = As[cur][r + 8][ks + tig + 4];
            }
#pragma unroll
            for (int nt = 0; nt < 8; nt++) {
                int cc = wn + nt * 8 + g;
                bf[nt][0] = Bs[cur][ks + tig][cc];
                bf[nt][1] = Bs[cur][ks + tig + 4][cc];
            }
#pragma unroll
            for (int mt = 0; mt < 2; mt++)
#pragma unroll
                for (int nt = 0; nt < 8; nt++)
                    mma_tf32(c[mt][nt], af[mt], bf[nt]);
        }

        if (has) {
            int nb = cur ^ 1;
            As[nb][aRow][aCol + 0] = f32_to_tf32(na0.x);
            As[nb][aRow][aCol + 1] = f32_to_tf32(na0.y);
            As[nb][aRow][aCol + 2] = f32_to_tf32(na0.z);
            As[nb][aRow][aCol + 3] = f32_to_tf32(na0.w);
            As[nb][aRow][aCol + 4] = f32_to_tf32(na1.x);
            As[nb][aRow][aCol + 5] = f32_to_tf32(na1.y);
            As[nb][aRow][aCol + 6] = f32_to_tf32(na1.z);
            As[nb][aRow][aCol + 7] = f32_to_tf32(na1.w);
            Bs[nb][bRow][bCol + 0] = f32_to_tf32(nb0.x);
            Bs[nb][bRow][bCol + 1] = f32_to_tf32(nb0.y);
            Bs[nb][bRow][bCol + 2] = f32_to_tf32(nb0.z);
            Bs[nb][bRow][bCol + 3] = f32_to_tf32(nb0.w);
            Bs[nb][bRow][bCol + 4] = f32_to_tf32(nb1.x);
            Bs[nb][bRow][bCol + 5] = f32_to_tf32(nb1.y);
            Bs[nb][bRow][bCol + 6] = f32_to_tf32(nb1.z);
            Bs[nb][bRow][bCol + 7] = f32_to_tf32(nb1.w);
            __syncthreads();
            cur = nb;
        }
    }

    // epilogue
#pragma unroll
    for (int mt = 0; mt < 2; mt++) {
        int rc0 = bm + wm + mt * 16 + g;
        int rc1 = rc0 + 8;
        bool v0 = true, v1 = true;
        int row0 = rc0, row1 = rc1;
        float s0 = 1.0f, s1 = 1.0f;
        if (SCATTER) {
            v0 = rc0 < count;
            v1 = rc1 < count;
            row0 = v0 ? idxL[rc0] : 0;
            row1 = v1 ? idxL[rc1] : 0;
            s0 = v0 ? gateL[rc0] : 0.0f;
            s1 = v1 ? gateL[rc1] : 0.0f;
        }
#pragma unroll
        for (int nt = 0; nt < 8; nt++) {
            int c0 = bn + wn + nt * 8 + tig * 2;
            float b0v = bias[c0], b1v = bias[c0 + 1];
            float v00 = c[mt][nt][0] + b0v;
            float v01 = c[mt][nt][1] + b1v;
            float v10 = c[mt][nt][2] + b0v;
            float v11 = c[mt][nt][3] + b1v;
            if (GELU) {
                v00 = gelu_tanh(v00); v01 = gelu_tanh(v01);
                v10 = gelu_tanh(v10); v11 = gelu_tanh(v11);
            }
            if (SCATTER) {
                if (v0) red_add_v2(C + (size_t)row0 * N + c0, s0 * v00, s0 * v01);
                if (v1) red_add_v2(C + (size_t)row1 * N + c0, s1 * v10, s1 * v11);
            } else {
                size_t o0 = (size_t)row0 * N + c0;
                size_t o1 = (size_t)row1 * N + c0;
                C[o0]     = v00;
                C[o0 + 1] = v01;
                C[o1]     = v10;
                C[o1 + 1] = v11;
            }
        }
    }
}

// ============================================================================
// launch
// ============================================================================
extern "C" void kernel_launch(void* const* d_in, const int* in_sizes, int n_in,
                              void* d_out, int out_size)
{
    const float* X  = (const float*)d_in[0];   // [8,2048,768]
    const float* W  = (const float*)d_in[1];   // [768,768]
    const float* b  = (const float*)d_in[2];   // [768]
    const float* Wg = (const float*)d_in[3];   // [768,4]
    const float* bg = (const float*)d_in[4];   // [4]
    const float* W1 = (const float*)d_in[5];   // [4,768,1024]
    const float* b1 = (const float*)d_in[6];   // [4,1024]
    const float* W2 = (const float*)d_in[7];   // [4,1024,768]
    const float* b2 = (const float*)d_in[8];   // [4,768]
    float* out = (float*)d_out;

    const int T = in_sizes[0] / DD;            // 16384

    float *h, *act, *gate, *Wf, *bf;
    int *idx, *cnt;
    cudaGetSymbolAddress((void**)&h,    g_h);
    cudaGetSymbolAddress((void**)&act,  g_act);
    cudaGetSymbolAddress((void**)&idx,  g_idx);
    cudaGetSymbolAddress((void**)&gate, g_gate);
    cudaGetSymbolAddress((void**)&cnt,  g_cnt);
    cudaGetSymbolAddress((void**)&Wf,   g_Wf);
    cudaGetSymbolAddress((void**)&bf,   g_bf);

    // 0) zero output (red.v2-accumulated) and routing state
    cudaMemsetAsync(out, 0, sizeof(float) * (size_t)T * DD);
    init_kernel<<<(EE * TT + 255) / 256, 256>>>(cnt, idx, gate);

    // 1) fused router weights: Wf = W@Wg, bf = b@Wg + bg   (fp32-exact-ish)
    fuse_wg_kernel<<<(DD + 1 + 7) / 8, 256>>>(W, Wg, b, bg, Wf, bf);

    // 2) router straight from X (fp32 logits) -> compacted token/gate lists
    router_kernel<<<T / 8, 256>>>(X, Wf, bf, idx, gate, cnt, T);

    // 3) dense projection h = X@W + b  (tf32 tensor cores; h only feeds tf32
    //    expert GEMMs now, so tf32 precision suffices)
    gemm_tf32_moe<false, false, false, false>
        <<<dim3(DD / 128, T / 128), 256>>>(
            X, W, b, nullptr, nullptr, cnt + EE, h, DD, DD);

    // 4) all experts' GEMM1 in one launch: act[e][rc] = gelu(h[idx] @ W1[e] + b1[e])
    gemm_tf32_moe<true, true, false, true>
        <<<dim3(DFFC / 128, T / 128, EE), 256>>>(
            h, W1, b1, idx, nullptr, cnt, act, DFFC, DD);

    // 5) all experts' GEMM2 in one launch:
    //    out[idx[rc]] += gate[rc] * (act[e][rc] @ W2[e] + b2[e])   (red.v2)
    gemm_tf32_moe<false, false, true, true>
        <<<dim3(DD / 128, T / 128, EE), 256>>>(
            act, W2, b2, idx, gate, cnt, out, DD, DFFC);
}